// round 4
// baseline (speedup 1.0000x reference)
#include <cuda_runtime.h>
#include <cuda_bf16.h>
#include <math.h>

// ---------------- problem constants ----------------
#define B_    4
#define L_    3136
#define DM_   192       // d_model
#define DIN_  384       // d_in
#define NS_   16        // n_state
#define KDIR_ 4
#define RED_  48
#define NCH_  16        // scan chunks
#define LCH_  196       // L_/NCH_
#define NR_   44        // dt_rank + 2*n_state
#define LOG2E 1.4426950408889634f

typedef unsigned long long u64;

// ---------------- f32x2 packed helpers (sm_103a FFMA2) ----------------
__device__ __forceinline__ u64 pack2(float lo, float hi) {
    u64 r; asm("mov.b64 %0,{%1,%2};" : "=l"(r) : "f"(lo), "f"(hi)); return r;
}
__device__ __forceinline__ void unpack2(u64 v, float& lo, float& hi) {
    asm("mov.b64 {%0,%1},%2;" : "=f"(lo), "=f"(hi) : "l"(v));
}
__device__ __forceinline__ u64 fma2(u64 a, u64 b, u64 c) {
    u64 d; asm("fma.rn.f32x2 %0,%1,%2,%3;" : "=l"(d) : "l"(a), "l"(b), "l"(c)); return d;
}
__device__ __forceinline__ u64 mul2(u64 a, u64 b) {
    u64 d; asm("mul.rn.f32x2 %0,%1,%2;" : "=l"(d) : "l"(a), "l"(b)); return d;
}

// ---------------- scratch (static device globals; no allocation) ----------------
__device__ float g_mask[B_ * L_];
__device__ __align__(16) float g_xz[(size_t)B_ * L_ * 2 * DIN_];            // (b,l,768)
__device__ __align__(16) float g_u[((size_t)KDIR_ * B_ * L_ + 128) * DIN_]; // (z,p,384) + pad
__device__ __align__(16) float g_xdbl[(size_t)KDIR_ * B_ * L_ * NR_];       // (z,p,44)
__device__ __align__(16) float g_Q[(size_t)KDIR_ * B_ * NCH_ * DIN_ * NS_];
__device__ float g_S[(size_t)KDIR_ * B_ * NCH_ * DIN_];
__device__ __align__(16) float g_y[(size_t)KDIR_ * B_ * L_ * DIN_];         // (z,l,384)
__device__ float g_gsum[KDIR_ * B_ * DIN_];
__device__ float g_catt[KDIR_ * B_ * DIN_];
__device__ int   g_flag[KDIR_ * B_ * 3 * NCH_];

// ---------------- direction permutation: scan position p -> original l ----------------
__device__ __forceinline__ int perm_idx(int k, int p) {
    int q = (k & 1) ? (L_ - 1 - p) : p;
    if (k < 2) return q;
    int wi = q % 7;
    int t  = q / 7;
    int hi = t % 7;
    int blk = t / 7;
    int wg = blk & 7, hg = blk >> 3;
    return (hg * 7 + hi) * 56 + wg * 7 + wi;
}

// rare exact-fallback path (A not the structured -(n+1) pattern)
__device__ __noinline__ void exp_general(float de, const float* __restrict__ A_log,
                                         int d, float* e) {
    #pragma unroll
    for (int n = 0; n < NS_; n++)
        e[n] = exp2f(de * (-__expf(A_log[d * NS_ + n])) * LOG2E);
}

__device__ __forceinline__ float softplusf(float s) {
    return (s > 20.f) ? s : log1pf(__expf(s));
}

// per-step: delta (packed dot), du pair, decay pairs e2[8]
__device__ __forceinline__ void step_compute(const float* __restrict__ row, float uu,
                                             const u64* wp, float bias, bool pok,
                                             const float* __restrict__ A_log, int d,
                                             u64* e2, float& de_out, u64& du2) {
    ulonglong2 X0 = *(const ulonglong2*)row;
    ulonglong2 X1 = *(const ulonglong2*)(row + 4);
    ulonglong2 X2 = *(const ulonglong2*)(row + 8);
    u64 s2 = mul2(X0.x, wp[0]);
    s2 = fma2(X0.y, wp[1], s2);
    s2 = fma2(X1.x, wp[2], s2);
    s2 = fma2(X1.y, wp[3], s2);
    s2 = fma2(X2.x, wp[4], s2);
    s2 = fma2(X2.y, wp[5], s2);
    float lo, hi; unpack2(s2, lo, hi);
    float de = softplusf(lo + hi + bias);
    float du = de * uu;
    du2 = pack2(du, du);
    if (pok) {
        float r = __expf(-de);
        float r2 = r * r;
        u64 rp = pack2(r2, r2);
        e2[0] = pack2(r, r2);
        #pragma unroll
        for (int i = 1; i < 8; i++) e2[i] = mul2(e2[i - 1], rp);
    } else {
        float ee[16];
        exp_general(de, A_log, d, ee);
        #pragma unroll
        for (int i = 0; i < 8; i++) e2[i] = pack2(ee[2 * i], ee[2 * i + 1]);
    }
    de_out = de;
}

// ---------------- mask: (x @ mask_w.T + mask_b) > 0 -> 1/0 ----------------
__global__ void k_mask(const float* __restrict__ X, const float* __restrict__ MW,
                       const float* __restrict__ MB) {
    int row = blockIdx.x * 8 + threadIdx.y;
    if (row >= B_ * L_) return;
    int lane = threadIdx.x;
    const float* xr = X + (size_t)row * DM_;
    float s = 0.f;
    for (int i = lane; i < DM_; i += 32) s += xr[i] * MW[i];
    #pragma unroll
    for (int o = 16; o; o >>= 1) s += __shfl_xor_sync(0xFFFFFFFFu, s, o);
    if (lane == 0) g_mask[row] = (s + MB[0] > 0.f) ? 1.f : 0.f;
}

// ---------------- xz = x @ in_proj_w.T : M=12544, N=768, K=192 (FFMA2) ----------------
__global__ __launch_bounds__(256) void k_xz(const float* __restrict__ X,
                                            const float* __restrict__ W) {
    __shared__ float4 As[128][9];
    __shared__ float4 Ws[64][9];
    int m0 = blockIdx.y * 128, n0 = blockIdx.x * 64;
    int tid = threadIdx.x;
    int tx = tid & 15, ty = tid >> 4;
    const float4* X4 = (const float4*)X;
    const float4* W4 = (const float4*)W;
    u64 acc2[8][4];
    #pragma unroll
    for (int i = 0; i < 8; i++)
        #pragma unroll
        for (int j = 0; j < 4; j++) acc2[i][j] = pack2(0.f, 0.f);
    for (int k0 = 0; k0 < 48; k0 += 8) {
        __syncthreads();
        #pragma unroll
        for (int i = 0; i < 4; i++) {
            int idx = tid + i * 256;
            int r = idx >> 3, kq = idx & 7;
            As[r][kq] = X4[(size_t)(m0 + r) * 48 + k0 + kq];
        }
        #pragma unroll
        for (int i = 0; i < 2; i++) {
            int idx = tid + i * 256;
            int r = idx >> 3, kq = idx & 7;
            Ws[r][kq] = W4[(size_t)(n0 + r) * 48 + k0 + kq];
        }
        __syncthreads();
        #pragma unroll
        for (int kq = 0; kq < 8; kq++) {
            ulonglong2 au[8];
            #pragma unroll
            for (int i = 0; i < 8; i++) au[i] = *(const ulonglong2*)&As[ty * 8 + i][kq];
            #pragma unroll
            for (int j = 0; j < 4; j++) {
                ulonglong2 w = *(const ulonglong2*)&Ws[tx + 16 * j][kq];
                #pragma unroll
                for (int i = 0; i < 8; i++) {
                    acc2[i][j] = fma2(au[i].x, w.x, acc2[i][j]);
                    acc2[i][j] = fma2(au[i].y, w.y, acc2[i][j]);
                }
            }
        }
    }
    #pragma unroll
    for (int i = 0; i < 8; i++)
        #pragma unroll
        for (int j = 0; j < 4; j++) {
            float lo, hi; unpack2(acc2[i][j], lo, hi);
            g_xz[(size_t)(m0 + ty * 8 + i) * 768 + n0 + tx + 16 * j] = lo + hi;
        }
}

// ---------------- depthwise causal conv + silu + mask -> u ----------------
__global__ void k_conv(const float* __restrict__ CW, const float* __restrict__ CB) {
    int z = blockIdx.z;
    int k = z / B_, b = z % B_;
    int tx = threadIdx.x;
    int d = blockIdx.y * 128 + tx;
    int p0 = blockIdx.x * 32;
    __shared__ float xs[35][128];
    __shared__ float ms[32];
    for (int i = 0; i < 35; i++) {
        int p = p0 - 3 + i;
        float v = 0.f;
        if (p >= 0) {
            int l = perm_idx(k, p);
            v = g_xz[((size_t)b * L_ + l) * (2 * DIN_) + d] * g_mask[b * L_ + l];
        }
        xs[i][tx] = v;
    }
    if (tx < 32) {
        int l = perm_idx(k, p0 + tx);
        ms[tx] = g_mask[b * L_ + l];
    }
    __syncthreads();
    float w0 = CW[d * 4 + 0], w1 = CW[d * 4 + 1], w2 = CW[d * 4 + 2], w3 = CW[d * 4 + 3];
    float cb = CB[d];
    float* ob = g_u + ((size_t)z * L_ + p0) * DIN_ + d;
    #pragma unroll 4
    for (int j = 0; j < 32; j++) {
        float s = w0 * xs[j][tx] + w1 * xs[j + 1][tx] + w2 * xs[j + 2][tx] + w3 * xs[j + 3][tx] + cb;
        float sil = s / (1.f + __expf(-s));
        ob[(size_t)j * DIN_] = sil * ms[j];
    }
}

// ---------------- x_dbl: per z, M=L (tiles of 128), N=44, K=384 (FFMA2) ----------------
__global__ __launch_bounds__(128) void k_xdbl(const float* __restrict__ XPW) {
    __shared__ float4 Us[128][9];
    __shared__ float4 Ws[NR_][9];
    int z = blockIdx.y;
    int k = z >> 2;
    int p0 = blockIdx.x * 128;
    int tid = threadIdx.x;
    int rq = tid & 3, pg = tid >> 2;
    const float4* U4 = (const float4*)g_u;
    const float4* W4 = (const float4*)XPW;
    u64 acc2[4][11];
    #pragma unroll
    for (int i = 0; i < 4; i++)
        #pragma unroll
        for (int j = 0; j < 11; j++) acc2[i][j] = pack2(0.f, 0.f);
    for (int k0 = 0; k0 < 96; k0 += 8) {
        __syncthreads();
        #pragma unroll
        for (int i = 0; i < 8; i++) {
            int idx = tid + i * 128;
            int r = idx >> 3, kq = idx & 7;
            Us[r][kq] = U4[((size_t)z * L_ + p0 + r) * 96 + k0 + kq];
        }
        #pragma unroll
        for (int i = 0; i < 3; i++) {
            int idx = tid + i * 128;
            if (idx < NR_ * 8) {
                int r = idx >> 3, kq = idx & 7;
                Ws[r][kq] = W4[((size_t)k * NR_ + r) * 96 + k0 + kq];
            }
        }
        __syncthreads();
        #pragma unroll
        for (int kq = 0; kq < 8; kq++) {
            ulonglong2 au[4];
            #pragma unroll
            for (int i = 0; i < 4; i++) au[i] = *(const ulonglong2*)&Us[pg * 4 + i][kq];
            #pragma unroll
            for (int j = 0; j < 11; j++) {
                ulonglong2 w = *(const ulonglong2*)&Ws[rq + 4 * j][kq];
                #pragma unroll
                for (int i = 0; i < 4; i++) {
                    acc2[i][j] = fma2(au[i].x, w.x, acc2[i][j]);
                    acc2[i][j] = fma2(au[i].y, w.y, acc2[i][j]);
                }
            }
        }
    }
    #pragma unroll
    for (int i = 0; i < 4; i++) {
        int p = p0 + pg * 4 + i;
        if (p < L_) {
            float* ob = g_xdbl + ((size_t)z * L_ + p) * NR_;
            #pragma unroll
            for (int j = 0; j < 11; j++) {
                float lo, hi; unpack2(acc2[i][j], lo, hi);
                ob[rq + 4 * j] = lo + hi;
            }
        }
    }
}

__global__ void k_zero() {
    int i = blockIdx.x * 256 + threadIdx.x;
    if (i < KDIR_ * B_ * DIN_) g_gsum[i] = 0.f;
    if (i < KDIR_ * B_ * 3 * NCH_) g_flag[i] = 0;
}

// ---------------- fused selective scan: local scan + decoupled lookback + replay ----------------
__global__ __launch_bounds__(128) void k_scan(const float* __restrict__ A_log,
                                              const float* __restrict__ DTW,
                                              const float* __restrict__ DTB,
                                              const float* __restrict__ Dsk) {
    int c = blockIdx.x;
    int dg = blockIdx.y;
    int z = blockIdx.z;
    int k = z >> 2, b = z & 3;
    int tid = threadIdx.x;
    int d = dg * 128 + tid;

    u64 wp[6];
    {
        const float* w = DTW + ((size_t)k * DIN_ + d) * 12;
        #pragma unroll
        for (int i = 0; i < 6; i++) wp[i] = pack2(w[2 * i], w[2 * i + 1]);
    }
    float bias = DTB[k * DIN_ + d];
    bool pok = true;
    #pragma unroll
    for (int n = 0; n < NS_; n++) {
        float an = -__expf(A_log[d * NS_ + n]);
        if (fabsf(an + (float)(n + 1)) > 1e-4f * (float)(n + 1)) pok = false;
    }
    const float* ul = g_u + ((size_t)z * L_ + c * LCH_) * DIN_ + d;
    const float* xr = g_xdbl + ((size_t)z * L_ + c * LCH_) * NR_;
    u64 zero2 = pack2(0.f, 0.f);

    // ---- pass A: local scan ----
    u64 h2[8];
    #pragma unroll
    for (int i = 0; i < 8; i++) h2[i] = zero2;
    float sdel = 0.f;
    for (int s = 0; s < LCH_; s++) {
        const float* row = xr + (size_t)s * NR_;
        float uu = ul[(size_t)s * DIN_];
        float de; u64 du2, e2[8];
        step_compute(row, uu, wp, bias, pok, A_log, d, e2, de, du2);
        const ulonglong2* bp = (const ulonglong2*)(row + 12);
        ulonglong2 B0 = bp[0], B1 = bp[1], B2 = bp[2], B3 = bp[3];
        u64 b2[8] = {B0.x, B0.y, B1.x, B1.y, B2.x, B2.y, B3.x, B3.y};
        #pragma unroll
        for (int i = 0; i < 8; i++) h2[i] = fma2(e2[i], h2[i], mul2(du2, b2[i]));
        sdel += de;
    }
    // publish aggregate
    {
        float4* q = (float4*)(g_Q + (((size_t)z * NCH_ + c) * DIN_ + d) * NS_);
        #pragma unroll
        for (int i = 0; i < 4; i++) {
            float a, bq, cq, dq;
            unpack2(h2[2 * i], a, bq);
            unpack2(h2[2 * i + 1], cq, dq);
            q[i] = make_float4(a, bq, cq, dq);
        }
        g_S[((size_t)z * NCH_ + c) * DIN_ + d] = sdel;
    }
    __threadfence();
    __syncthreads();
    int fbase = (z * 3 + dg) * NCH_;
    if (tid == 0) atomicExch(&g_flag[fbase + c], 1);

    // ---- pass B: lookback -> h_start ----
    if (c > 0) {
        u64 one2 = pack2(1.f, 1.f);
        u64 P2[8], hs2[8];
        #pragma unroll
        for (int i = 0; i < 8; i++) { P2[i] = one2; hs2[i] = zero2; }
        for (int j = c - 1; j >= 0; j--) {
            if (tid == 0) { while (atomicAdd(&g_flag[fbase + j], 0) == 0) {} }
            __syncthreads();
            const float4* q = (const float4*)(g_Q + (((size_t)z * NCH_ + j) * DIN_ + d) * NS_);
            #pragma unroll
            for (int i = 0; i < 4; i++) {
                float4 qv = __ldcg(q + i);
                hs2[2 * i]     = fma2(P2[2 * i],     pack2(qv.x, qv.y), hs2[2 * i]);
                hs2[2 * i + 1] = fma2(P2[2 * i + 1], pack2(qv.z, qv.w), hs2[2 * i + 1]);
            }
            if (j > 0) {
                float Sj = __ldcg(&g_S[((size_t)z * NCH_ + j) * DIN_ + d]);
                if (pok) {
                    float rho = __expf(-Sj);
                    float rho2 = rho * rho;
                    u64 rp = pack2(rho2, rho2);
                    u64 t = pack2(rho, rho2);
                    P2[0] = mul2(P2[0], t);
                    #pragma unroll
                    for (int i = 1; i < 8; i++) { t = mul2(t, rp); P2[i] = mul2(P2[i], t); }
                } else {
                    float ee[16];
                    exp_general(Sj, A_log, d, ee);
                    #pragma unroll
                    for (int i = 0; i < 8; i++) P2[i] = mul2(P2[i], pack2(ee[2 * i], ee[2 * i + 1]));
                }
            }
        }
        #pragma unroll
        for (int i = 0; i < 8; i++) h2[i] = hs2[i];
    } else {
        #pragma unroll
        for (int i = 0; i < 8; i++) h2[i] = zero2;
    }

    // ---- pass C: replay, emit y ----
    float dsk = Dsk[d];
    for (int s = 0; s < LCH_; s++) {
        const float* row = xr + (size_t)s * NR_;
        float uu = ul[(size_t)s * DIN_];
        float de; u64 du2, e2[8];
        step_compute(row, uu, wp, bias, pok, A_log, d, e2, de, du2);
        const ulonglong2* bp = (const ulonglong2*)(row + 12);
        const ulonglong2* cp = (const ulonglong2*)(row + 28);
        ulonglong2 B0 = bp[0], B1 = bp[1], B2 = bp[2], B3 = bp[3];
        ulonglong2 C0 = cp[0], C1 = cp[1], C2 = cp[2], C3 = cp[3];
        u64 b2[8] = {B0.x, B0.y, B1.x, B1.y, B2.x, B2.y, B3.x, B3.y};
        u64 c2[8] = {C0.x, C0.y, C1.x, C1.y, C2.x, C2.y, C3.x, C3.y};
        #pragma unroll
        for (int i = 0; i < 8; i++) h2[i] = fma2(e2[i], h2[i], mul2(du2, b2[i]));
        u64 y2 = mul2(h2[0], c2[0]);
        #pragma unroll
        for (int i = 1; i < 8; i++) y2 = fma2(h2[i], c2[i], y2);
        float ylo, yhi; unpack2(y2, ylo, yhi);
        float y = ylo + yhi + dsk * uu;
        int p = c * LCH_ + s;
        int l = perm_idx(k, p);
        float zv = g_xz[((size_t)b * L_ + l) * (2 * DIN_) + DIN_ + d];
        y *= zv / (1.f + __expf(-zv));
        g_y[((size_t)z * L_ + l) * DIN_ + d] = y;
    }
}

// ---------------- LayerNorm over d, warp-per-row, accumulate per-(z,d) sum of xn ----------------
__global__ __launch_bounds__(384) void k_lnstats(const float* __restrict__ G,
                                                 const float* __restrict__ Bt) {
    int kdir = blockIdx.z, b = blockIdx.y;
    int z = kdir * B_ + b;
    int tid = threadIdx.x;
    int w = tid >> 5, lane = tid & 31;
    int gw = blockIdx.x * 12 + w;
    float gr[12], br[12], acc[12];
    #pragma unroll
    for (int j = 0; j < 12; j++) {
        int d = lane + 32 * j;
        gr[j] = G[d]; br[j] = Bt[d]; acc[j] = 0.f;
    }
    for (int l = gw; l < L_; l += 192) {
        const float* yr = g_y + ((size_t)z * L_ + l) * DIN_;
        float v[12];
        float s1 = 0.f, s2 = 0.f;
        #pragma unroll
        for (int j = 0; j < 12; j++) {
            v[j] = yr[lane + 32 * j];
            s1 += v[j];
            s2 += v[j] * v[j];
        }
        #pragma unroll
        for (int o = 16; o; o >>= 1) {
            s1 += __shfl_xor_sync(0xFFFFFFFFu, s1, o);
            s2 += __shfl_xor_sync(0xFFFFFFFFu, s2, o);
        }
        float mu = s1 * (1.f / DIN_);
        float var = s2 * (1.f / DIN_) - mu * mu;
        float rstd = rsqrtf(var + 1e-5f);
        #pragma unroll
        for (int j = 0; j < 12; j++)
            acc[j] += (v[j] - mu) * rstd * gr[j] + br[j];
    }
    #pragma unroll
    for (int j = 0; j < 12; j++)
        atomicAdd(&g_gsum[z * DIN_ + lane + 32 * j], acc[j]);
}

// ---------------- channel attention ----------------
__global__ void k_attn(const float* __restrict__ RW, const float* __restrict__ RB,
                       const float* __restrict__ SW, const float* __restrict__ SB) {
    int z = blockIdx.x;
    __shared__ float gg[DIN_];
    __shared__ float tt[RED_];
    int d = threadIdx.x;
    int lane = d & 31, wid = d >> 5;
    gg[d] = g_gsum[z * DIN_ + d] * (1.f / (float)L_);
    __syncthreads();
    #pragma unroll
    for (int jj = 0; jj < 4; jj++) {
        int j = wid * 4 + jj;
        float s = 0.f;
        for (int i = lane; i < DIN_; i += 32) s += gg[i] * RW[(size_t)j * DIN_ + i];
        #pragma unroll
        for (int o = 16; o; o >>= 1) s += __shfl_xor_sync(0xFFFFFFFFu, s, o);
        if (lane == 0) {
            float v = s + RB[j];
            tt[j] = 0.5f * v * (1.f + erff(v * 0.70710678118f));
        }
    }
    __syncthreads();
    float s = SB[d];
    #pragma unroll
    for (int j = 0; j < RED_; j++) s += tt[j] * SW[(size_t)d * RED_ + j];
    g_catt[z * DIN_ + d] = 1.f / (1.f + __expf(-s));
}

// ---------------- out = (sum_k y_k * catt_k) @ out_proj.T + bias (FFMA2) ----------------
__global__ __launch_bounds__(256) void k_out(const float* __restrict__ W,
                                             const float* __restrict__ BI,
                                             float* __restrict__ OUT) {
    __shared__ float4 As[64][9];
    __shared__ float4 Ws[192][9];
    int m0 = blockIdx.x * 64;
    int b = m0 / L_;
    int l0 = m0 - b * L_;
    int tid = threadIdx.x;
    int tx = tid & 15, ty = tid >> 4;
    const float4* Y4 = (const float4*)g_y;
    const float4* C4 = (const float4*)g_catt;
    const float4* W4 = (const float4*)W;
    u64 acc2[4][12];
    #pragma unroll
    for (int i = 0; i < 4; i++)
        #pragma unroll
        for (int j = 0; j < 12; j++) acc2[i][j] = pack2(0.f, 0.f);
    for (int k0 = 0; k0 < 96; k0 += 8) {
        __syncthreads();
        #pragma unroll
        for (int i = 0; i < 2; i++) {
            int idx = tid + i * 256;
            int r = idx >> 3, kq = idx & 7;
            float4 s = {0.f, 0.f, 0.f, 0.f};
            #pragma unroll
            for (int dir = 0; dir < KDIR_; dir++) {
                float4 y4 = Y4[((size_t)(dir * B_ + b) * L_ + l0 + r) * 96 + k0 + kq];
                float4 c4 = C4[(size_t)(dir * B_ + b) * 96 + k0 + kq];
                s.x += y4.x * c4.x; s.y += y4.y * c4.y;
                s.z += y4.z * c4.z; s.w += y4.w * c4.w;
            }
            As[r][kq] = s;
        }
        #pragma unroll
        for (int i = 0; i < 6; i++) {
            int idx = tid + i * 256;
            int r = idx >> 3, kq = idx & 7;
            Ws[r][kq] = W4[(size_t)r * 96 + k0 + kq];
        }
        __syncthreads();
        #pragma unroll
        for (int kq = 0; kq < 8; kq++) {
            ulonglong2 au[4];
            #pragma unroll
            for (int i = 0; i < 4; i++) au[i] = *(const ulonglong2*)&As[ty * 4 + i][kq];
            #pragma unroll
            for (int j = 0; j < 12; j++) {
                ulonglong2 w = *(const ulonglong2*)&Ws[tx + 16 * j][kq];
                #pragma unroll
                for (int i = 0; i < 4; i++) {
                    acc2[i][j] = fma2(au[i].x, w.x, acc2[i][j]);
                    acc2[i][j] = fma2(au[i].y, w.y, acc2[i][j]);
                }
            }
        }
    }
    #pragma unroll
    for (int i = 0; i < 4; i++)
        #pragma unroll
        for (int j = 0; j < 12; j++) {
            float lo, hi; unpack2(acc2[i][j], lo, hi);
            OUT[(size_t)(m0 + ty * 4 + i) * DM_ + tx + 16 * j] = lo + hi + BI[tx + 16 * j];
        }
}

// ---------------- launch ----------------
extern "C" void kernel_launch(void* const* d_in, const int* in_sizes, int n_in,
                              void* d_out, int out_size) {
    const float* x          = (const float*)d_in[0];
    const float* in_proj_w  = (const float*)d_in[1];
    const float* conv_w     = (const float*)d_in[2];
    const float* conv_b     = (const float*)d_in[3];
    const float* x_proj_w   = (const float*)d_in[4];
    const float* dt_w       = (const float*)d_in[5];
    const float* dt_b       = (const float*)d_in[6];
    const float* A_log      = (const float*)d_in[7];
    const float* D_skip     = (const float*)d_in[8];
    const float* out_proj_w = (const float*)d_in[9];
    const float* out_proj_b = (const float*)d_in[10];
    const float* ln_g       = (const float*)d_in[11];
    const float* ln_b       = (const float*)d_in[12];
    const float* red_w      = (const float*)d_in[13];
    const float* red_b      = (const float*)d_in[14];
    const float* sel_w      = (const float*)d_in[15];
    const float* sel_b      = (const float*)d_in[16];
    const float* mask_w     = (const float*)d_in[17];
    const float* mask_b     = (const float*)d_in[18];
    float* out = (float*)d_out;

    k_mask<<<dim3((B_ * L_ + 7) / 8), dim3(32, 8)>>>(x, mask_w, mask_b);
    k_zero<<<24, 256>>>();
    k_xz<<<dim3(12, 98), 256>>>(x, in_proj_w);
    k_conv<<<dim3(L_ / 32, 3, KDIR_ * B_), 128>>>(conv_w, conv_b);
    k_xdbl<<<dim3(25, KDIR_ * B_), 128>>>(x_proj_w);
    k_scan<<<dim3(NCH_, 3, KDIR_ * B_), 128>>>(A_log, dt_w, dt_b, D_skip);
    k_lnstats<<<dim3(16, B_, KDIR_), 384>>>(ln_g, ln_b);
    k_attn<<<KDIR_ * B_, DIN_>>>(red_w, red_b, sel_w, sel_b);
    k_out<<<dim3(196), 256>>>(out_proj_w, out_proj_b, out);
}

// round 5
// speedup vs baseline: 1.2786x; 1.2786x over previous
#include <cuda_runtime.h>
#include <cuda_bf16.h>
#include <math.h>

// ---------------- problem constants ----------------
#define B_    4
#define L_    3136
#define DM_   192       // d_model
#define DIN_  384       // d_in
#define NS_   16        // n_state
#define KDIR_ 4
#define RED_  48
#define NCH_  49        // scan chunks
#define LCH_  64        // L_/NCH_
#define NR_   44        // dt_rank + 2*n_state
#define LOG2E 1.4426950408889634f

typedef unsigned long long u64;

// ---------------- f32x2 packed helpers (sm_103a FFMA2) ----------------
__device__ __forceinline__ u64 pack2(float lo, float hi) {
    u64 r; asm("mov.b64 %0,{%1,%2};" : "=l"(r) : "f"(lo), "f"(hi)); return r;
}
__device__ __forceinline__ void unpack2(u64 v, float& lo, float& hi) {
    asm("mov.b64 {%0,%1},%2;" : "=f"(lo), "=f"(hi) : "l"(v));
}
__device__ __forceinline__ u64 fma2(u64 a, u64 b, u64 c) {
    u64 d; asm("fma.rn.f32x2 %0,%1,%2,%3;" : "=l"(d) : "l"(a), "l"(b), "l"(c)); return d;
}
__device__ __forceinline__ u64 mul2(u64 a, u64 b) {
    u64 d; asm("mul.rn.f32x2 %0,%1,%2;" : "=l"(d) : "l"(a), "l"(b)); return d;
}

// ---------------- scratch (static device globals; no allocation) ----------------
__device__ float g_mask[B_ * L_];
__device__ __align__(16) float g_xz[(size_t)B_ * L_ * 2 * DIN_];            // (b,l,768)
__device__ __align__(16) float g_u[((size_t)KDIR_ * B_ * L_ + 128) * DIN_]; // (z,p,384) + pad
__device__ __align__(16) float g_xdbl[(size_t)KDIR_ * B_ * L_ * NR_];       // (z,p,44)
__device__ __align__(16) float g_delta[(size_t)KDIR_ * B_ * L_ * DIN_];     // (z,p,384)
__device__ __align__(16) float g_Q[(size_t)KDIR_ * B_ * NCH_ * DIN_ * NS_];
__device__ float g_S[(size_t)KDIR_ * B_ * NCH_ * DIN_];
__device__ __align__(16) float g_Hs[(size_t)KDIR_ * B_ * NCH_ * DIN_ * NS_];
__device__ __align__(16) float g_y[(size_t)KDIR_ * B_ * L_ * DIN_];         // (z,l,384)
__device__ float g_gsum[KDIR_ * B_ * DIN_];
__device__ float g_catt[KDIR_ * B_ * DIN_];

// ---------------- direction permutation: scan position p -> original l ----------------
__device__ __forceinline__ int perm_idx(int k, int p) {
    int q = (k & 1) ? (L_ - 1 - p) : p;
    if (k < 2) return q;
    int wi = q % 7;
    int t  = q / 7;
    int hi = t % 7;
    int blk = t / 7;
    int wg = blk & 7, hg = blk >> 3;
    return (hg * 7 + hi) * 56 + wg * 7 + wi;
}

// rare exact-fallback path (A not the structured -(n+1) pattern)
__device__ __noinline__ void exp_general(float de, const float* __restrict__ A_log,
                                         int d, float* e) {
    #pragma unroll
    for (int n = 0; n < NS_; n++)
        e[n] = exp2f(de * (-__expf(A_log[d * NS_ + n])) * LOG2E);
}

__device__ __forceinline__ float softplusf(float s) {
    return (s > 20.f) ? s : log1pf(__expf(s));
}

// decay pairs e2[i] = (r^(2i+1), r^(2i+2)) via shallow tree
__device__ __forceinline__ void decay_pairs(float de, bool pok,
                                            const float* __restrict__ A_log, int d,
                                            u64* e2) {
    if (pok) {
        float r = __expf(-de);
        float r2 = r * r, r4 = r2 * r2, r8 = r4 * r4;
        u64 p2 = pack2(r2, r2), p4 = pack2(r4, r4), p8 = pack2(r8, r8);
        e2[0] = pack2(r, r2);
        e2[1] = mul2(e2[0], p2);
        e2[2] = mul2(e2[0], p4);
        e2[3] = mul2(e2[1], p4);
        e2[4] = mul2(e2[0], p8);
        e2[5] = mul2(e2[1], p8);
        e2[6] = mul2(e2[2], p8);
        e2[7] = mul2(e2[3], p8);
    } else {
        float ee[16];
        exp_general(de, A_log, d, ee);
        #pragma unroll
        for (int i = 0; i < 8; i++) e2[i] = pack2(ee[2 * i], ee[2 * i + 1]);
    }
}

// ---------------- mask: (x @ mask_w.T + mask_b) > 0 -> 1/0 ----------------
__global__ void k_mask(const float* __restrict__ X, const float* __restrict__ MW,
                       const float* __restrict__ MB) {
    int row = blockIdx.x * 8 + threadIdx.y;
    if (row >= B_ * L_) return;
    int lane = threadIdx.x;
    const float* xr = X + (size_t)row * DM_;
    float s = 0.f;
    for (int i = lane; i < DM_; i += 32) s += xr[i] * MW[i];
    #pragma unroll
    for (int o = 16; o; o >>= 1) s += __shfl_xor_sync(0xFFFFFFFFu, s, o);
    if (lane == 0) g_mask[row] = (s + MB[0] > 0.f) ? 1.f : 0.f;
}

// ---------------- xz = x @ in_proj_w.T : M=12544, N=768, K=192 (FFMA2) ----------------
__global__ __launch_bounds__(256) void k_xz(const float* __restrict__ X,
                                            const float* __restrict__ W) {
    __shared__ float4 As[128][9];
    __shared__ float4 Ws[64][9];
    int m0 = blockIdx.y * 128, n0 = blockIdx.x * 64;
    int tid = threadIdx.x;
    int tx = tid & 15, ty = tid >> 4;
    const float4* X4 = (const float4*)X;
    const float4* W4 = (const float4*)W;
    u64 acc2[8][4];
    #pragma unroll
    for (int i = 0; i < 8; i++)
        #pragma unroll
        for (int j = 0; j < 4; j++) acc2[i][j] = pack2(0.f, 0.f);
    for (int k0 = 0; k0 < 48; k0 += 8) {
        __syncthreads();
        #pragma unroll
        for (int i = 0; i < 4; i++) {
            int idx = tid + i * 256;
            int r = idx >> 3, kq = idx & 7;
            As[r][kq] = X4[(size_t)(m0 + r) * 48 + k0 + kq];
        }
        #pragma unroll
        for (int i = 0; i < 2; i++) {
            int idx = tid + i * 256;
            int r = idx >> 3, kq = idx & 7;
            Ws[r][kq] = W4[(size_t)(n0 + r) * 48 + k0 + kq];
        }
        __syncthreads();
        #pragma unroll
        for (int kq = 0; kq < 8; kq++) {
            ulonglong2 au[8];
            #pragma unroll
            for (int i = 0; i < 8; i++) au[i] = *(const ulonglong2*)&As[ty * 8 + i][kq];
            #pragma unroll
            for (int j = 0; j < 4; j++) {
                ulonglong2 w = *(const ulonglong2*)&Ws[tx + 16 * j][kq];
                #pragma unroll
                for (int i = 0; i < 8; i++) {
                    acc2[i][j] = fma2(au[i].x, w.x, acc2[i][j]);
                    acc2[i][j] = fma2(au[i].y, w.y, acc2[i][j]);
                }
            }
        }
    }
    #pragma unroll
    for (int i = 0; i < 8; i++)
        #pragma unroll
        for (int j = 0; j < 4; j++) {
            float lo, hi; unpack2(acc2[i][j], lo, hi);
            g_xz[(size_t)(m0 + ty * 8 + i) * 768 + n0 + tx + 16 * j] = lo + hi;
        }
}

// ---------------- depthwise causal conv + silu + mask -> u ----------------
__global__ void k_conv(const float* __restrict__ CW, const float* __restrict__ CB) {
    int z = blockIdx.z;
    int k = z / B_, b = z % B_;
    int tx = threadIdx.x;
    int d = blockIdx.y * 128 + tx;
    int p0 = blockIdx.x * 32;
    __shared__ float xs[35][128];
    __shared__ float ms[32];
    __shared__ int   ls[35];
    if (tx < 35) {
        int p = p0 - 3 + tx;
        ls[tx] = (p >= 0) ? perm_idx(k, p) : -1;
    }
    __syncthreads();
    for (int i = 0; i < 35; i++) {
        int l = ls[i];
        float v = 0.f;
        if (l >= 0) v = g_xz[((size_t)b * L_ + l) * (2 * DIN_) + d] * g_mask[b * L_ + l];
        xs[i][tx] = v;
    }
    if (tx < 32) ms[tx] = g_mask[b * L_ + ls[tx + 3]];
    __syncthreads();
    float w0 = CW[d * 4 + 0], w1 = CW[d * 4 + 1], w2 = CW[d * 4 + 2], w3 = CW[d * 4 + 3];
    float cb = CB[d];
    float* ob = g_u + ((size_t)z * L_ + p0) * DIN_ + d;
    #pragma unroll 4
    for (int j = 0; j < 32; j++) {
        float s = w0 * xs[j][tx] + w1 * xs[j + 1][tx] + w2 * xs[j + 2][tx] + w3 * xs[j + 3][tx] + cb;
        float sil = s / (1.f + __expf(-s));
        ob[(size_t)j * DIN_] = sil * ms[j];
    }
}

// ---------------- x_dbl: per z, M=L (tiles of 128), N=44, K=384 (FFMA2) ----------------
__global__ __launch_bounds__(128) void k_xdbl(const float* __restrict__ XPW) {
    __shared__ float4 Us[128][9];
    __shared__ float4 Ws[NR_][9];
    int z = blockIdx.y;
    int k = z >> 2;
    int p0 = blockIdx.x * 128;
    int tid = threadIdx.x;
    int rq = tid & 3, pg = tid >> 2;
    const float4* U4 = (const float4*)g_u;
    const float4* W4 = (const float4*)XPW;
    u64 acc2[4][11];
    #pragma unroll
    for (int i = 0; i < 4; i++)
        #pragma unroll
        for (int j = 0; j < 11; j++) acc2[i][j] = pack2(0.f, 0.f);
    for (int k0 = 0; k0 < 96; k0 += 8) {
        __syncthreads();
        #pragma unroll
        for (int i = 0; i < 8; i++) {
            int idx = tid + i * 128;
            int r = idx >> 3, kq = idx & 7;
            Us[r][kq] = U4[((size_t)z * L_ + p0 + r) * 96 + k0 + kq];
        }
        #pragma unroll
        for (int i = 0; i < 3; i++) {
            int idx = tid + i * 128;
            if (idx < NR_ * 8) {
                int r = idx >> 3, kq = idx & 7;
                Ws[r][kq] = W4[((size_t)k * NR_ + r) * 96 + k0 + kq];
            }
        }
        __syncthreads();
        #pragma unroll
        for (int kq = 0; kq < 8; kq++) {
            ulonglong2 au[4];
            #pragma unroll
            for (int i = 0; i < 4; i++) au[i] = *(const ulonglong2*)&Us[pg * 4 + i][kq];
            #pragma unroll
            for (int j = 0; j < 11; j++) {
                ulonglong2 w = *(const ulonglong2*)&Ws[rq + 4 * j][kq];
                #pragma unroll
                for (int i = 0; i < 4; i++) {
                    acc2[i][j] = fma2(au[i].x, w.x, acc2[i][j]);
                    acc2[i][j] = fma2(au[i].y, w.y, acc2[i][j]);
                }
            }
        }
    }
    #pragma unroll
    for (int i = 0; i < 4; i++) {
        int p = p0 + pg * 4 + i;
        if (p < L_) {
            float* ob = g_xdbl + ((size_t)z * L_ + p) * NR_;
            #pragma unroll
            for (int j = 0; j < 11; j++) {
                float lo, hi; unpack2(acc2[i][j], lo, hi);
                ob[rq + 4 * j] = lo + hi;
            }
        }
    }
}

// ---------------- delta = softplus(x_dbl[:,:12] @ dt_w.T + dt_b) ----------------
__global__ __launch_bounds__(384) void k_delta(const float* __restrict__ DTW,
                                               const float* __restrict__ DTB) {
    int z = blockIdx.y;
    int k = z >> 2;
    int p0 = blockIdx.x * 64;
    __shared__ float xd[64][12];
    int tid = threadIdx.x;
    for (int i = tid; i < 64 * 12; i += 384) {
        int pl = i / 12, r = i % 12;
        xd[pl][r] = g_xdbl[((size_t)z * L_ + p0 + pl) * NR_ + r];
    }
    __syncthreads();
    int d = tid;
    float wt[12];
    #pragma unroll
    for (int r = 0; r < 12; r++) wt[r] = DTW[((size_t)k * DIN_ + d) * 12 + r];
    float bias = DTB[k * DIN_ + d];
    float* ob = g_delta + ((size_t)z * L_ + p0) * DIN_ + d;
    #pragma unroll 4
    for (int pl = 0; pl < 64; pl++) {
        float s = bias;
        #pragma unroll
        for (int r = 0; r < 12; r++) s += xd[pl][r] * wt[r];
        ob[(size_t)pl * DIN_] = softplusf(s);
    }
}

__global__ void k_zero() {
    int i = blockIdx.x * 256 + threadIdx.x;
    if (i < KDIR_ * B_ * DIN_) g_gsum[i] = 0.f;
}

// ---------------- scan pass 1: per-chunk local scan, summaries (Q, sum delta) ----------------
__global__ __launch_bounds__(128) void k_scan1(const float* __restrict__ A_log) {
    int z = blockIdx.z;
    int d = blockIdx.y * 128 + threadIdx.x;
    int c = blockIdx.x;
    bool pok = true;
    #pragma unroll
    for (int n = 0; n < NS_; n++) {
        float an = -__expf(A_log[d * NS_ + n]);
        if (fabsf(an + (float)(n + 1)) > 1e-4f * (float)(n + 1)) pok = false;
    }
    const float* dl = g_delta + ((size_t)z * L_ + c * LCH_) * DIN_ + d;
    const float* ul = g_u + ((size_t)z * L_ + c * LCH_) * DIN_ + d;
    const float* xr = g_xdbl + ((size_t)z * L_ + c * LCH_) * NR_;
    u64 zero2 = pack2(0.f, 0.f);
    u64 h2[8];
    #pragma unroll
    for (int i = 0; i < 8; i++) h2[i] = zero2;
    float sdel = 0.f;
    for (int s = 0; s < LCH_; s++) {
        float de = dl[(size_t)s * DIN_];
        float uu = ul[(size_t)s * DIN_];
        float du = de * uu;
        u64 du2 = pack2(du, du);
        u64 e2[8];
        decay_pairs(de, pok, A_log, d, e2);
        const ulonglong2* bp = (const ulonglong2*)(xr + (size_t)s * NR_ + 12);
        ulonglong2 B0 = bp[0], B1 = bp[1];
        h2[0] = fma2(e2[0], h2[0], mul2(du2, B0.x));
        h2[1] = fma2(e2[1], h2[1], mul2(du2, B0.y));
        h2[2] = fma2(e2[2], h2[2], mul2(du2, B1.x));
        h2[3] = fma2(e2[3], h2[3], mul2(du2, B1.y));
        ulonglong2 B2 = bp[2], B3 = bp[3];
        h2[4] = fma2(e2[4], h2[4], mul2(du2, B2.x));
        h2[5] = fma2(e2[5], h2[5], mul2(du2, B2.y));
        h2[6] = fma2(e2[6], h2[6], mul2(du2, B3.x));
        h2[7] = fma2(e2[7], h2[7], mul2(du2, B3.y));
        sdel += de;
    }
    float4* q = (float4*)(g_Q + (((size_t)z * NCH_ + c) * DIN_ + d) * NS_);
    #pragma unroll
    for (int i = 0; i < 4; i++) {
        float a, bq, cq, dq;
        unpack2(h2[2 * i], a, bq);
        unpack2(h2[2 * i + 1], cq, dq);
        q[i] = make_float4(a, bq, cq, dq);
    }
    g_S[((size_t)z * NCH_ + c) * DIN_ + d] = sdel;
}

// ---------------- scan fix: prefix over chunks -> h_start per chunk ----------------
__global__ void k_fix(const float* __restrict__ A_log) {
    int z = blockIdx.x;
    int d = threadIdx.x;
    float a2[NS_];
    #pragma unroll
    for (int n = 0; n < NS_; n++) a2[n] = -__expf(A_log[d * NS_ + n]) * LOG2E;
    float hs[NS_];
    #pragma unroll
    for (int n = 0; n < NS_; n++) hs[n] = 0.f;
    for (int c = 0; c < NCH_; c++) {
        float* H = g_Hs + (((size_t)z * NCH_ + c) * DIN_ + d) * NS_;
        #pragma unroll
        for (int n = 0; n < NS_; n++) H[n] = hs[n];
        float sd = g_S[((size_t)z * NCH_ + c) * DIN_ + d];
        const float* Q = g_Q + (((size_t)z * NCH_ + c) * DIN_ + d) * NS_;
        #pragma unroll
        for (int n = 0; n < NS_; n++) hs[n] = exp2f(a2[n] * sd) * hs[n] + Q[n];
    }
}

// ---------------- scan pass 2: replay with h_start, emit y*silu(z), scatter ----------------
__global__ __launch_bounds__(128) void k_scan2(const float* __restrict__ A_log,
                                               const float* __restrict__ Dsk) {
    int z = blockIdx.z;
    int k = z >> 2, b = z & 3;
    int d = blockIdx.y * 128 + threadIdx.x;
    int c = blockIdx.x;
    __shared__ int ls[LCH_];
    if (threadIdx.x < LCH_) ls[threadIdx.x] = perm_idx(k, c * LCH_ + threadIdx.x);
    bool pok = true;
    #pragma unroll
    for (int n = 0; n < NS_; n++) {
        float an = -__expf(A_log[d * NS_ + n]);
        if (fabsf(an + (float)(n + 1)) > 1e-4f * (float)(n + 1)) pok = false;
    }
    const float* dl = g_delta + ((size_t)z * L_ + c * LCH_) * DIN_ + d;
    const float* ul = g_u + ((size_t)z * L_ + c * LCH_) * DIN_ + d;
    const float* xr = g_xdbl + ((size_t)z * L_ + c * LCH_) * NR_;
    const float* H = g_Hs + (((size_t)z * NCH_ + c) * DIN_ + d) * NS_;
    u64 h2[8];
    {
        const float4* h4 = (const float4*)H;
        #pragma unroll
        for (int i = 0; i < 4; i++) {
            float4 v = h4[i];
            h2[2 * i] = pack2(v.x, v.y);
            h2[2 * i + 1] = pack2(v.z, v.w);
        }
    }
    float dsk = Dsk[d];
    __syncthreads();
    for (int s = 0; s < LCH_; s++) {
        float de = dl[(size_t)s * DIN_];
        float uu = ul[(size_t)s * DIN_];
        float du = de * uu;
        u64 du2 = pack2(du, du);
        u64 e2[8];
        decay_pairs(de, pok, A_log, d, e2);
        const ulonglong2* bp = (const ulonglong2*)(xr + (size_t)s * NR_ + 12);
        const ulonglong2* cp = (const ulonglong2*)(xr + (size_t)s * NR_ + 28);
        ulonglong2 B0 = bp[0], B1 = bp[1], B2 = bp[2], B3 = bp[3];
        ulonglong2 C0 = cp[0], C1 = cp[1], C2 = cp[2], C3 = cp[3];
        h2[0] = fma2(e2[0], h2[0], mul2(du2, B0.x));
        h2[1] = fma2(e2[1], h2[1], mul2(du2, B0.y));
        h2[2] = fma2(e2[2], h2[2], mul2(du2, B1.x));
        h2[3] = fma2(e2[3], h2[3], mul2(du2, B1.y));
        h2[4] = fma2(e2[4], h2[4], mul2(du2, B2.x));
        h2[5] = fma2(e2[5], h2[5], mul2(du2, B2.y));
        h2[6] = fma2(e2[6], h2[6], mul2(du2, B3.x));
        h2[7] = fma2(e2[7], h2[7], mul2(du2, B3.y));
        u64 y2 = mul2(h2[0], C0.x);
        y2 = fma2(h2[1], C0.y, y2);
        y2 = fma2(h2[2], C1.x, y2);
        y2 = fma2(h2[3], C1.y, y2);
        y2 = fma2(h2[4], C2.x, y2);
        y2 = fma2(h2[5], C2.y, y2);
        y2 = fma2(h2[6], C3.x, y2);
        y2 = fma2(h2[7], C3.y, y2);
        float ylo, yhi; unpack2(y2, ylo, yhi);
        float y = ylo + yhi + dsk * uu;
        int l = ls[s];
        float zv = g_xz[((size_t)b * L_ + l) * (2 * DIN_) + DIN_ + d];
        y *= zv / (1.f + __expf(-zv));
        g_y[((size_t)z * L_ + l) * DIN_ + d] = y;
    }
}

// ---------------- LayerNorm over d, warp-per-row, accumulate per-(z,d) sum of xn ----------------
__global__ __launch_bounds__(384) void k_lnstats(const float* __restrict__ G,
                                                 const float* __restrict__ Bt) {
    int kdir = blockIdx.z, b = blockIdx.y;
    int z = kdir * B_ + b;
    int tid = threadIdx.x;
    int w = tid >> 5, lane = tid & 31;
    int gw = blockIdx.x * 12 + w;
    float gr[12], br[12], acc[12];
    #pragma unroll
    for (int j = 0; j < 12; j++) {
        int d = lane + 32 * j;
        gr[j] = G[d]; br[j] = Bt[d]; acc[j] = 0.f;
    }
    for (int l = gw; l < L_; l += 192) {
        const float* yr = g_y + ((size_t)z * L_ + l) * DIN_;
        float v[12];
        float s1 = 0.f, s2 = 0.f;
        #pragma unroll
        for (int j = 0; j < 12; j++) {
            v[j] = yr[lane + 32 * j];
            s1 += v[j];
            s2 += v[j] * v[j];
        }
        #pragma unroll
        for (int o = 16; o; o >>= 1) {
            s1 += __shfl_xor_sync(0xFFFFFFFFu, s1, o);
            s2 += __shfl_xor_sync(0xFFFFFFFFu, s2, o);
        }
        float mu = s1 * (1.f / DIN_);
        float var = s2 * (1.f / DIN_) - mu * mu;
        float rstd = rsqrtf(var + 1e-5f);
        #pragma unroll
        for (int j = 0; j < 12; j++)
            acc[j] += (v[j] - mu) * rstd * gr[j] + br[j];
    }
    #pragma unroll
    for (int j = 0; j < 12; j++)
        atomicAdd(&g_gsum[z * DIN_ + lane + 32 * j], acc[j]);
}

// ---------------- channel attention ----------------
__global__ void k_attn(const float* __restrict__ RW, const float* __restrict__ RB,
                       const float* __restrict__ SW, const float* __restrict__ SB) {
    int z = blockIdx.x;
    __shared__ float gg[DIN_];
    __shared__ float tt[RED_];
    int d = threadIdx.x;
    int lane = d & 31, wid = d >> 5;
    gg[d] = g_gsum[z * DIN_ + d] * (1.f / (float)L_);
    __syncthreads();
    #pragma unroll
    for (int jj = 0; jj < 4; jj++) {
        int j = wid * 4 + jj;
        float s = 0.f;
        for (int i = lane; i < DIN_; i += 32) s += gg[i] * RW[(size_t)j * DIN_ + i];
        #pragma unroll
        for (int o = 16; o; o >>= 1) s += __shfl_xor_sync(0xFFFFFFFFu, s, o);
        if (lane == 0) {
            float v = s + RB[j];
            tt[j] = 0.5f * v * (1.f + erff(v * 0.70710678118f));
        }
    }
    __syncthreads();
    float s = SB[d];
    #pragma unroll
    for (int j = 0; j < RED_; j++) s += tt[j] * SW[(size_t)d * RED_ + j];
    g_catt[z * DIN_ + d] = 1.f / (1.f + __expf(-s));
}

// ---------------- out = (sum_k y_k * catt_k) @ out_proj.T + bias (FFMA2) ----------------
__global__ __launch_bounds__(256) void k_out(const float* __restrict__ W,
                                             const float* __restrict__ BI,
                                             float* __restrict__ OUT) {
    __shared__ float4 As[64][9];
    __shared__ float4 Ws[192][9];
    int m0 = blockIdx.x * 64;
    int b = m0 / L_;
    int l0 = m0 - b * L_;
    int tid = threadIdx.x;
    int tx = tid & 15, ty = tid >> 4;
    const float4* Y4 = (const float4*)g_y;
    const float4* C4 = (const float4*)g_catt;
    const float4* W4 = (const float4*)W;
    u64 acc2[4][12];
    #pragma unroll
    for (int i = 0; i < 4; i++)
        #pragma unroll
        for (int j = 0; j < 12; j++) acc2[i][j] = pack2(0.f, 0.f);
    for (int k0 = 0; k0 < 96; k0 += 8) {
        __syncthreads();
        #pragma unroll
        for (int i = 0; i < 2; i++) {
            int idx = tid + i * 256;
            int r = idx >> 3, kq = idx & 7;
            float4 s = {0.f, 0.f, 0.f, 0.f};
            #pragma unroll
            for (int dir = 0; dir < KDIR_; dir++) {
                float4 y4 = Y4[((size_t)(dir * B_ + b) * L_ + l0 + r) * 96 + k0 + kq];
                float4 c4 = C4[(size_t)(dir * B_ + b) * 96 + k0 + kq];
                s.x += y4.x * c4.x; s.y += y4.y * c4.y;
                s.z += y4.z * c4.z; s.w += y4.w * c4.w;
            }
            As[r][kq] = s;
        }
        #pragma unroll
        for (int i = 0; i < 6; i++) {
            int idx = tid + i * 256;
            int r = idx >> 3, kq = idx & 7;
            Ws[r][kq] = W4[(size_t)r * 96 + k0 + kq];
        }
        __syncthreads();
        #pragma unroll
        for (int kq = 0; kq < 8; kq++) {
            ulonglong2 au[4];
            #pragma unroll
            for (int i = 0; i < 4; i++) au[i] = *(const ulonglong2*)&As[ty * 4 + i][kq];
            #pragma unroll
            for (int j = 0; j < 12; j++) {
                ulonglong2 w = *(const ulonglong2*)&Ws[tx + 16 * j][kq];
                #pragma unroll
                for (int i = 0; i < 4; i++) {
                    acc2[i][j] = fma2(au[i].x, w.x, acc2[i][j]);
                    acc2[i][j] = fma2(au[i].y, w.y, acc2[i][j]);
                }
            }
        }
    }
    #pragma unroll
    for (int i = 0; i < 4; i++)
        #pragma unroll
        for (int j = 0; j < 12; j++) {
            float lo, hi; unpack2(acc2[i][j], lo, hi);
            OUT[(size_t)(m0 + ty * 4 + i) * DM_ + tx + 16 * j] = lo + hi + BI[tx + 16 * j];
        }
}

// ---------------- launch ----------------
extern "C" void kernel_launch(void* const* d_in, const int* in_sizes, int n_in,
                              void* d_out, int out_size) {
    const float* x          = (const float*)d_in[0];
    const float* in_proj_w  = (const float*)d_in[1];
    const float* conv_w     = (const float*)d_in[2];
    const float* conv_b     = (const float*)d_in[3];
    const float* x_proj_w   = (const float*)d_in[4];
    const float* dt_w       = (const float*)d_in[5];
    const float* dt_b       = (const float*)d_in[6];
    const float* A_log      = (const float*)d_in[7];
    const float* D_skip     = (const float*)d_in[8];
    const float* out_proj_w = (const float*)d_in[9];
    const float* out_proj_b = (const float*)d_in[10];
    const float* ln_g       = (const float*)d_in[11];
    const float* ln_b       = (const float*)d_in[12];
    const float* red_w      = (const float*)d_in[13];
    const float* red_b      = (const float*)d_in[14];
    const float* sel_w      = (const float*)d_in[15];
    const float* sel_b      = (const float*)d_in[16];
    const float* mask_w     = (const float*)d_in[17];
    const float* mask_b     = (const float*)d_in[18];
    float* out = (float*)d_out;

    k_mask<<<dim3((B_ * L_ + 7) / 8), dim3(32, 8)>>>(x, mask_w, mask_b);
    k_zero<<<24, 256>>>();
    k_xz<<<dim3(12, 98), 256>>>(x, in_proj_w);
    k_conv<<<dim3(L_ / 32, 3, KDIR_ * B_), 128>>>(conv_w, conv_b);
    k_xdbl<<<dim3(25, KDIR_ * B_), 128>>>(x_proj_w);
    k_delta<<<dim3(49, KDIR_ * B_), 384>>>(dt_w, dt_b);
    k_scan1<<<dim3(NCH_, 3, KDIR_ * B_), 128>>>(A_log);
    k_fix<<<KDIR_ * B_, DIN_>>>(A_log);
    k_scan2<<<dim3(NCH_, 3, KDIR_ * B_), 128>>>(A_log, D_skip);
    k_lnstats<<<dim3(16, B_, KDIR_), 384>>>(ln_g, ln_b);
    k_attn<<<KDIR_ * B_, DIN_>>>(red_w, red_b, sel_w, sel_b);
    k_out<<<dim3(196), 256>>>(out_proj_w, out_proj_b, out);
}

// round 6
// speedup vs baseline: 1.3712x; 1.0725x over previous
#include <cuda_runtime.h>
#include <cuda_bf16.h>
#include <math.h>

// ---------------- problem constants ----------------
#define B_    4
#define L_    3136
#define DM_   192       // d_model
#define DIN_  384       // d_in
#define NS_   16        // n_state
#define KDIR_ 4
#define RED_  48
#define NCH_  49        // scan chunks
#define LCH_  64        // L_/NCH_
#define NR_   44        // dt_rank + 2*n_state
#define LOG2E 1.4426950408889634f

typedef unsigned long long u64;

// ---------------- f32x2 packed helpers (sm_103a FFMA2) ----------------
__device__ __forceinline__ u64 pack2(float lo, float hi) {
    u64 r; asm("mov.b64 %0,{%1,%2};" : "=l"(r) : "f"(lo), "f"(hi)); return r;
}
__device__ __forceinline__ void unpack2(u64 v, float& lo, float& hi) {
    asm("mov.b64 {%0,%1},%2;" : "=f"(lo), "=f"(hi) : "l"(v));
}
__device__ __forceinline__ u64 fma2(u64 a, u64 b, u64 c) {
    u64 d; asm("fma.rn.f32x2 %0,%1,%2,%3;" : "=l"(d) : "l"(a), "l"(b), "l"(c)); return d;
}
__device__ __forceinline__ u64 mul2(u64 a, u64 b) {
    u64 d; asm("mul.rn.f32x2 %0,%1,%2;" : "=l"(d) : "l"(a), "l"(b)); return d;
}

// ---------------- scratch (static device globals; no allocation) ----------------
__device__ float g_mask[B_ * L_];
__device__ __align__(16) float g_xz[(size_t)B_ * L_ * 2 * DIN_];            // (b,l,768)
__device__ __align__(16) float g_u[((size_t)KDIR_ * B_ * L_ + 128) * DIN_]; // (z,p,384) + pad
__device__ __align__(16) float g_xdbl[(size_t)KDIR_ * B_ * L_ * NR_];       // (z,p,44)
__device__ __align__(16) u64   g_Q[(size_t)KDIR_ * B_ * NCH_ * 8 * DIN_];   // pair-plane
__device__ float g_S[(size_t)KDIR_ * B_ * NCH_ * DIN_];
__device__ __align__(16) u64   g_Hs[(size_t)KDIR_ * B_ * NCH_ * 8 * DIN_];  // pair-plane
__device__ __align__(16) float g_y[(size_t)KDIR_ * B_ * L_ * DIN_];         // (z,l,384)
__device__ float g_gsum[KDIR_ * B_ * DIN_];
__device__ float g_catt[KDIR_ * B_ * DIN_];

// ---------------- direction permutation: scan position p -> original l ----------------
__device__ __forceinline__ int perm_idx(int k, int p) {
    int q = (k & 1) ? (L_ - 1 - p) : p;
    if (k < 2) return q;
    int wi = q % 7;
    int t  = q / 7;
    int hi = t % 7;
    int blk = t / 7;
    int wg = blk & 7, hg = blk >> 3;
    return (hg * 7 + hi) * 56 + wg * 7 + wi;
}

// rare exact-fallback path (A not the structured -(n+1) pattern)
__device__ __noinline__ void exp_general(float de, const float* __restrict__ A_log,
                                         int d, float* e) {
    #pragma unroll
    for (int n = 0; n < NS_; n++)
        e[n] = exp2f(de * (-__expf(A_log[d * NS_ + n])) * LOG2E);
}

// e2[i] = (r^(2i+1), r^(2i+2)) via shallow tree
__device__ __forceinline__ void decay_from_r(float r, u64* e2) {
    float r2 = r * r, r4 = r2 * r2, r8 = r4 * r4;
    u64 p2 = pack2(r2, r2), p4 = pack2(r4, r4), p8 = pack2(r8, r8);
    e2[0] = pack2(r, r2);
    e2[1] = mul2(e2[0], p2);
    e2[2] = mul2(e2[0], p4);
    e2[3] = mul2(e2[1], p4);
    e2[4] = mul2(e2[0], p8);
    e2[5] = mul2(e2[1], p8);
    e2[6] = mul2(e2[2], p8);
    e2[7] = mul2(e2[3], p8);
}

// ---------------- mask + gsum zero ----------------
__global__ void k_mask(const float* __restrict__ X, const float* __restrict__ MW,
                       const float* __restrict__ MB) {
    int t = blockIdx.x * 256 + threadIdx.y * 32 + threadIdx.x;
    if (t < KDIR_ * B_ * DIN_) g_gsum[t] = 0.f;
    int row = blockIdx.x * 8 + threadIdx.y;
    if (row >= B_ * L_) return;
    int lane = threadIdx.x;
    const float* xr = X + (size_t)row * DM_;
    float s = 0.f;
    for (int i = lane; i < DM_; i += 32) s += xr[i] * MW[i];
    #pragma unroll
    for (int o = 16; o; o >>= 1) s += __shfl_xor_sync(0xFFFFFFFFu, s, o);
    if (lane == 0) g_mask[row] = (s + MB[0] > 0.f) ? 1.f : 0.f;
}

// ---------------- xz = x @ in_proj_w.T : M=12544, N=768, K=192 (FFMA2) ----------------
__global__ __launch_bounds__(256) void k_xz(const float* __restrict__ X,
                                            const float* __restrict__ W) {
    __shared__ float4 As[128][9];
    __shared__ float4 Ws[64][9];
    int m0 = blockIdx.y * 128, n0 = blockIdx.x * 64;
    int tid = threadIdx.x;
    int tx = tid & 15, ty = tid >> 4;
    const float4* X4 = (const float4*)X;
    const float4* W4 = (const float4*)W;
    u64 acc2[8][4];
    #pragma unroll
    for (int i = 0; i < 8; i++)
        #pragma unroll
        for (int j = 0; j < 4; j++) acc2[i][j] = pack2(0.f, 0.f);
    for (int k0 = 0; k0 < 48; k0 += 8) {
        __syncthreads();
        #pragma unroll
        for (int i = 0; i < 4; i++) {
            int idx = tid + i * 256;
            int r = idx >> 3, kq = idx & 7;
            As[r][kq] = X4[(size_t)(m0 + r) * 48 + k0 + kq];
        }
        #pragma unroll
        for (int i = 0; i < 2; i++) {
            int idx = tid + i * 256;
            int r = idx >> 3, kq = idx & 7;
            Ws[r][kq] = W4[(size_t)(n0 + r) * 48 + k0 + kq];
        }
        __syncthreads();
        #pragma unroll
        for (int kq = 0; kq < 8; kq++) {
            ulonglong2 au[8];
            #pragma unroll
            for (int i = 0; i < 8; i++) au[i] = *(const ulonglong2*)&As[ty * 8 + i][kq];
            #pragma unroll
            for (int j = 0; j < 4; j++) {
                ulonglong2 w = *(const ulonglong2*)&Ws[tx + 16 * j][kq];
                #pragma unroll
                for (int i = 0; i < 8; i++) {
                    acc2[i][j] = fma2(au[i].x, w.x, acc2[i][j]);
                    acc2[i][j] = fma2(au[i].y, w.y, acc2[i][j]);
                }
            }
        }
    }
    #pragma unroll
    for (int i = 0; i < 8; i++)
        #pragma unroll
        for (int j = 0; j < 4; j++) {
            float lo, hi; unpack2(acc2[i][j], lo, hi);
            g_xz[(size_t)(m0 + ty * 8 + i) * 768 + n0 + tx + 16 * j] = lo + hi;
        }
}

// ---------------- depthwise causal conv + silu + mask -> u ----------------
__global__ void k_conv(const float* __restrict__ CW, const float* __restrict__ CB) {
    int z = blockIdx.z;
    int k = z / B_, b = z % B_;
    int tx = threadIdx.x;
    int d = blockIdx.y * 128 + tx;
    int p0 = blockIdx.x * 32;
    __shared__ float xs[35][128];
    __shared__ float ms[32];
    __shared__ int   ls[35];
    if (tx < 35) {
        int p = p0 - 3 + tx;
        ls[tx] = (p >= 0) ? perm_idx(k, p) : -1;
    }
    __syncthreads();
    for (int i = 0; i < 35; i++) {
        int l = ls[i];
        float v = 0.f;
        if (l >= 0) v = g_xz[((size_t)b * L_ + l) * (2 * DIN_) + d] * g_mask[b * L_ + l];
        xs[i][tx] = v;
    }
    if (tx < 32) ms[tx] = g_mask[b * L_ + ls[tx + 3]];
    __syncthreads();
    float w0 = CW[d * 4 + 0], w1 = CW[d * 4 + 1], w2 = CW[d * 4 + 2], w3 = CW[d * 4 + 3];
    float cb = CB[d];
    float* ob = g_u + ((size_t)z * L_ + p0) * DIN_ + d;
    #pragma unroll 4
    for (int j = 0; j < 32; j++) {
        float s = w0 * xs[j][tx] + w1 * xs[j + 1][tx] + w2 * xs[j + 2][tx] + w3 * xs[j + 3][tx] + cb;
        float sil = s / (1.f + __expf(-s));
        ob[(size_t)j * DIN_] = sil * ms[j];
    }
}

// ---------------- x_dbl: per z, M=L (tiles of 128), N=44, K=384 (FFMA2) ----------------
__global__ __launch_bounds__(128) void k_xdbl(const float* __restrict__ XPW) {
    __shared__ float4 Us[128][9];
    __shared__ float4 Ws[NR_][9];
    int z = blockIdx.y;
    int k = z >> 2;
    int p0 = blockIdx.x * 128;
    int tid = threadIdx.x;
    int rq = tid & 3, pg = tid >> 2;
    const float4* U4 = (const float4*)g_u;
    const float4* W4 = (const float4*)XPW;
    u64 acc2[4][11];
    #pragma unroll
    for (int i = 0; i < 4; i++)
        #pragma unroll
        for (int j = 0; j < 11; j++) acc2[i][j] = pack2(0.f, 0.f);
    for (int k0 = 0; k0 < 96; k0 += 8) {
        __syncthreads();
        #pragma unroll
        for (int i = 0; i < 8; i++) {
            int idx = tid + i * 128;
            int r = idx >> 3, kq = idx & 7;
            Us[r][kq] = U4[((size_t)z * L_ + p0 + r) * 96 + k0 + kq];
        }
        #pragma unroll
        for (int i = 0; i < 3; i++) {
            int idx = tid + i * 128;
            if (idx < NR_ * 8) {
                int r = idx >> 3, kq = idx & 7;
                Ws[r][kq] = W4[((size_t)k * NR_ + r) * 96 + k0 + kq];
            }
        }
        __syncthreads();
        #pragma unroll
        for (int kq = 0; kq < 8; kq++) {
            ulonglong2 au[4];
            #pragma unroll
            for (int i = 0; i < 4; i++) au[i] = *(const ulonglong2*)&Us[pg * 4 + i][kq];
            #pragma unroll
            for (int j = 0; j < 11; j++) {
                ulonglong2 w = *(const ulonglong2*)&Ws[rq + 4 * j][kq];
                #pragma unroll
                for (int i = 0; i < 4; i++) {
                    acc2[i][j] = fma2(au[i].x, w.x, acc2[i][j]);
                    acc2[i][j] = fma2(au[i].y, w.y, acc2[i][j]);
                }
            }
        }
    }
    #pragma unroll
    for (int i = 0; i < 4; i++) {
        int p = p0 + pg * 4 + i;
        if (p < L_) {
            float* ob = g_xdbl + ((size_t)z * L_ + p) * NR_;
            #pragma unroll
            for (int j = 0; j < 11; j++) {
                float lo, hi; unpack2(acc2[i][j], lo, hi);
                ob[rq + 4 * j] = lo + hi;
            }
        }
    }
}

// ---------------- scan pass 1: local scan with fused delta; publish Q (pair-plane) + S ----------------
__global__ __launch_bounds__(128) void k_scan1(const float* __restrict__ A_log,
                                               const float* __restrict__ DTW,
                                               const float* __restrict__ DTB) {
    int z = blockIdx.z;
    int k = z >> 2;
    int d = blockIdx.y * 128 + threadIdx.x;
    int c = blockIdx.x;
    u64 wp[6];
    {
        const float* w = DTW + ((size_t)k * DIN_ + d) * 12;
        #pragma unroll
        for (int i = 0; i < 6; i++) wp[i] = pack2(w[2 * i], w[2 * i + 1]);
    }
    float bias = DTB[k * DIN_ + d];
    bool pok = true;
    #pragma unroll
    for (int n = 0; n < NS_; n++) {
        float an = -__expf(A_log[d * NS_ + n]);
        if (fabsf(an + (float)(n + 1)) > 1e-4f * (float)(n + 1)) pok = false;
    }
    const float* ul = g_u + ((size_t)z * L_ + c * LCH_) * DIN_ + d;
    const float* xr = g_xdbl + ((size_t)z * L_ + c * LCH_) * NR_;
    u64 h2[8];
    #pragma unroll
    for (int i = 0; i < 8; i++) h2[i] = pack2(0.f, 0.f);
    float rprod = 1.f, sdel = 0.f;
    #pragma unroll 2
    for (int s = 0; s < LCH_; s++) {
        const float* row = xr + (size_t)s * NR_;
        ulonglong2 X0 = *(const ulonglong2*)row;
        ulonglong2 X1 = *(const ulonglong2*)(row + 4);
        ulonglong2 X2 = *(const ulonglong2*)(row + 8);
        u64 s2 = mul2(X0.x, wp[0]);
        s2 = fma2(X0.y, wp[1], s2);
        s2 = fma2(X1.x, wp[2], s2);
        s2 = fma2(X1.y, wp[3], s2);
        s2 = fma2(X2.x, wp[4], s2);
        s2 = fma2(X2.y, wp[5], s2);
        float lo, hi; unpack2(s2, lo, hi);
        float sv = lo + hi + bias;
        float t = __expf(sv);
        float de = (sv > 20.f) ? sv : log1pf(t);
        float uu = ul[(size_t)s * DIN_];
        float du = de * uu;
        u64 du2 = pack2(du, du);
        u64 e2[8];
        if (pok) {
            float r = 1.f / (1.f + t);      // exp(-softplus(sv))
            decay_from_r(r, e2);
            rprod *= r;
        } else {
            float ee[16];
            exp_general(de, A_log, d, ee);
            #pragma unroll
            for (int i = 0; i < 8; i++) e2[i] = pack2(ee[2 * i], ee[2 * i + 1]);
            sdel += de;
        }
        const ulonglong2* bp = (const ulonglong2*)(row + 12);
        ulonglong2 B0 = bp[0], B1 = bp[1], B2 = bp[2], B3 = bp[3];
        h2[0] = fma2(e2[0], h2[0], mul2(du2, B0.x));
        h2[1] = fma2(e2[1], h2[1], mul2(du2, B0.y));
        h2[2] = fma2(e2[2], h2[2], mul2(du2, B1.x));
        h2[3] = fma2(e2[3], h2[3], mul2(du2, B1.y));
        h2[4] = fma2(e2[4], h2[4], mul2(du2, B2.x));
        h2[5] = fma2(e2[5], h2[5], mul2(du2, B2.y));
        h2[6] = fma2(e2[6], h2[6], mul2(du2, B3.x));
        h2[7] = fma2(e2[7], h2[7], mul2(du2, B3.y));
    }
    u64* q = g_Q + ((size_t)z * NCH_ + c) * 8 * DIN_ + d;
    #pragma unroll
    for (int i = 0; i < 8; i++) q[(size_t)i * DIN_] = h2[i];
    g_S[((size_t)z * NCH_ + c) * DIN_ + d] = pok ? rprod : sdel;
}

// ---------------- scan fix: prefix over chunks (parallel over z x dgroup, prefetched) ----------------
__global__ __launch_bounds__(128) void k_fix(const float* __restrict__ A_log) {
    int z = blockIdx.x;
    int dg = blockIdx.y;
    int d = dg * 128 + threadIdx.x;
    bool pok = true;
    float a2[NS_];
    #pragma unroll
    for (int n = 0; n < NS_; n++) {
        float an = -__expf(A_log[d * NS_ + n]);
        a2[n] = an * LOG2E;
        if (fabsf(an + (float)(n + 1)) > 1e-4f * (float)(n + 1)) pok = false;
    }
    const u64* Q = g_Q + (size_t)z * NCH_ * 8 * DIN_ + d;
    u64* H = g_Hs + (size_t)z * NCH_ * 8 * DIN_ + d;
    const float* S = g_S + (size_t)z * NCH_ * DIN_ + d;
    u64 hs2[8];
    #pragma unroll
    for (int i = 0; i < 8; i++) hs2[i] = pack2(0.f, 0.f);
    u64 qc[8]; float Sc;
    #pragma unroll
    for (int i = 0; i < 8; i++) qc[i] = Q[(size_t)i * DIN_];
    Sc = S[0];
    for (int c = 0; c < NCH_; c++) {
        u64 qn[8]; float Sn = 0.f;
        if (c + 1 < NCH_) {
            const u64* Qn = Q + (size_t)(c + 1) * 8 * DIN_;
            #pragma unroll
            for (int i = 0; i < 8; i++) qn[i] = Qn[(size_t)i * DIN_];
            Sn = S[(size_t)(c + 1) * DIN_];
        }
        u64* Hc = H + (size_t)c * 8 * DIN_;
        #pragma unroll
        for (int i = 0; i < 8; i++) Hc[(size_t)i * DIN_] = hs2[i];
        u64 e2[8];
        if (pok) {
            decay_from_r(Sc, e2);        // Sc = prod of r over chunk
        } else {
            float ee[16];
            #pragma unroll
            for (int n = 0; n < NS_; n++) ee[n] = exp2f(a2[n] * Sc);
            #pragma unroll
            for (int i = 0; i < 8; i++) e2[i] = pack2(ee[2 * i], ee[2 * i + 1]);
        }
        #pragma unroll
        for (int i = 0; i < 8; i++) hs2[i] = fma2(e2[i], hs2[i], qc[i]);
        #pragma unroll
        for (int i = 0; i < 8; i++) qc[i] = qn[i];
        Sc = Sn;
    }
}

// ---------------- scan pass 2: replay with h_start (fused delta), emit y*silu(z) ----------------
__global__ __launch_bounds__(128) void k_scan2(const float* __restrict__ A_log,
                                               const float* __restrict__ DTW,
                                               const float* __restrict__ DTB,
                                               const float* __restrict__ Dsk) {
    int z = blockIdx.z;
    int k = z >> 2, b = z & 3;
    int d = blockIdx.y * 128 + threadIdx.x;
    int c = blockIdx.x;
    __shared__ int ls[LCH_];
    if (threadIdx.x < LCH_) ls[threadIdx.x] = perm_idx(k, c * LCH_ + threadIdx.x);
    u64 wp[6];
    {
        const float* w = DTW + ((size_t)k * DIN_ + d) * 12;
        #pragma unroll
        for (int i = 0; i < 6; i++) wp[i] = pack2(w[2 * i], w[2 * i + 1]);
    }
    float bias = DTB[k * DIN_ + d];
    bool pok = true;
    #pragma unroll
    for (int n = 0; n < NS_; n++) {
        float an = -__expf(A_log[d * NS_ + n]);
        if (fabsf(an + (float)(n + 1)) > 1e-4f * (float)(n + 1)) pok = false;
    }
    const float* ul = g_u + ((size_t)z * L_ + c * LCH_) * DIN_ + d;
    const float* xr = g_xdbl + ((size_t)z * L_ + c * LCH_) * NR_;
    const u64* H = g_Hs + ((size_t)z * NCH_ + c) * 8 * DIN_ + d;
    u64 h2[8];
    #pragma unroll
    for (int i = 0; i < 8; i++) h2[i] = H[(size_t)i * DIN_];
    float dsk = Dsk[d];
    __syncthreads();
    for (int s = 0; s < LCH_; s++) {
        const float* row = xr + (size_t)s * NR_;
        ulonglong2 X0 = *(const ulonglong2*)row;
        ulonglong2 X1 = *(const ulonglong2*)(row + 4);
        ulonglong2 X2 = *(const ulonglong2*)(row + 8);
        u64 s2 = mul2(X0.x, wp[0]);
        s2 = fma2(X0.y, wp[1], s2);
        s2 = fma2(X1.x, wp[2], s2);
        s2 = fma2(X1.y, wp[3], s2);
        s2 = fma2(X2.x, wp[4], s2);
        s2 = fma2(X2.y, wp[5], s2);
        float lo, hi; unpack2(s2, lo, hi);
        float sv = lo + hi + bias;
        float t = __expf(sv);
        float de = (sv > 20.f) ? sv : log1pf(t);
        float uu = ul[(size_t)s * DIN_];
        float du = de * uu;
        u64 du2 = pack2(du, du);
        u64 e2[8];
        if (pok) {
            float r = 1.f / (1.f + t);
            decay_from_r(r, e2);
        } else {
            float ee[16];
            exp_general(de, A_log, d, ee);
            #pragma unroll
            for (int i = 0; i < 8; i++) e2[i] = pack2(ee[2 * i], ee[2 * i + 1]);
        }
        const ulonglong2* bp = (const ulonglong2*)(row + 12);
        const ulonglong2* cp = (const ulonglong2*)(row + 28);
        ulonglong2 B0 = bp[0], B1 = bp[1], B2 = bp[2], B3 = bp[3];
        ulonglong2 C0 = cp[0], C1 = cp[1], C2 = cp[2], C3 = cp[3];
        h2[0] = fma2(e2[0], h2[0], mul2(du2, B0.x));
        h2[1] = fma2(e2[1], h2[1], mul2(du2, B0.y));
        h2[2] = fma2(e2[2], h2[2], mul2(du2, B1.x));
        h2[3] = fma2(e2[3], h2[3], mul2(du2, B1.y));
        h2[4] = fma2(e2[4], h2[4], mul2(du2, B2.x));
        h2[5] = fma2(e2[5], h2[5], mul2(du2, B2.y));
        h2[6] = fma2(e2[6], h2[6], mul2(du2, B3.x));
        h2[7] = fma2(e2[7], h2[7], mul2(du2, B3.y));
        u64 y2 = mul2(h2[0], C0.x);
        y2 = fma2(h2[1], C0.y, y2);
        y2 = fma2(h2[2], C1.x, y2);
        y2 = fma2(h2[3], C1.y, y2);
        y2 = fma2(h2[4], C2.x, y2);
        y2 = fma2(h2[5], C2.y, y2);
        y2 = fma2(h2[6], C3.x, y2);
        y2 = fma2(h2[7], C3.y, y2);
        float ylo, yhi; unpack2(y2, ylo, yhi);
        float y = ylo + yhi + dsk * uu;
        int l = ls[s];
        float zv = g_xz[((size_t)b * L_ + l) * (2 * DIN_) + DIN_ + d];
        y *= zv / (1.f + __expf(-zv));
        g_y[((size_t)z * L_ + l) * DIN_ + d] = y;
    }
}

// ---------------- LayerNorm over d, warp-per-row, accumulate per-(z,d) sum of xn ----------------
__global__ __launch_bounds__(384) void k_lnstats(const float* __restrict__ G,
                                                 const float* __restrict__ Bt) {
    int kdir = blockIdx.z, b = blockIdx.y;
    int z = kdir * B_ + b;
    int tid = threadIdx.x;
    int w = tid >> 5, lane = tid & 31;
    int gw = blockIdx.x * 12 + w;
    float gr[12], br[12], acc[12];
    #pragma unroll
    for (int j = 0; j < 12; j++) {
        int d = lane + 32 * j;
        gr[j] = G[d]; br[j] = Bt[d]; acc[j] = 0.f;
    }
    for (int l = gw; l < L_; l += 192) {
        const float* yr = g_y + ((size_t)z * L_ + l) * DIN_;
        float v[12];
        float s1 = 0.f, s2 = 0.f;
        #pragma unroll
        for (int j = 0; j < 12; j++) {
            v[j] = yr[lane + 32 * j];
            s1 += v[j];
            s2 += v[j] * v[j];
        }
        #pragma unroll
        for (int o = 16; o; o >>= 1) {
            s1 += __shfl_xor_sync(0xFFFFFFFFu, s1, o);
            s2 += __shfl_xor_sync(0xFFFFFFFFu, s2, o);
        }
        float mu = s1 * (1.f / DIN_);
        float var = s2 * (1.f / DIN_) - mu * mu;
        float rstd = rsqrtf(var + 1e-5f);
        #pragma unroll
        for (int j = 0; j < 12; j++)
            acc[j] += (v[j] - mu) * rstd * gr[j] + br[j];
    }
    #pragma unroll
    for (int j = 0; j < 12; j++)
        atomicAdd(&g_gsum[z * DIN_ + lane + 32 * j], acc[j]);
}

// ---------------- channel attention ----------------
__global__ void k_attn(const float* __restrict__ RW, const float* __restrict__ RB,
                       const float* __restrict__ SW, const float* __restrict__ SB) {
    int z = blockIdx.x;
    __shared__ float gg[DIN_];
    __shared__ float tt[RED_];
    int d = threadIdx.x;
    int lane = d & 31, wid = d >> 5;
    gg[d] = g_gsum[z * DIN_ + d] * (1.f / (float)L_);
    __syncthreads();
    #pragma unroll
    for (int jj = 0; jj < 4; jj++) {
        int j = wid * 4 + jj;
        float s = 0.f;
        for (int i = lane; i < DIN_; i += 32) s += gg[i] * RW[(size_t)j * DIN_ + i];
        #pragma unroll
        for (int o = 16; o; o >>= 1) s += __shfl_xor_sync(0xFFFFFFFFu, s, o);
        if (lane == 0) {
            float v = s + RB[j];
            tt[j] = 0.5f * v * (1.f + erff(v * 0.70710678118f));
        }
    }
    __syncthreads();
    float s = SB[d];
    #pragma unroll
    for (int j = 0; j < RED_; j++) s += tt[j] * SW[(size_t)d * RED_ + j];
    g_catt[z * DIN_ + d] = 1.f / (1.f + __expf(-s));
}

// ---------------- out = (sum_k y_k * catt_k) @ out_proj.T + bias (FFMA2, 32M x 192N) ----------------
__global__ __launch_bounds__(128) void k_out(const float* __restrict__ W,
                                             const float* __restrict__ BI,
                                             float* __restrict__ OUT) {
    __shared__ float4 As[32][9];
    __shared__ float4 Ws[192][9];
    int m0 = blockIdx.x * 32;
    int b = m0 / L_;
    int l0 = m0 - b * L_;
    int tid = threadIdx.x;
    int tx = tid & 15, ty = tid >> 4;   // ty 0..7
    const float4* Y4 = (const float4*)g_y;
    const float4* C4 = (const float4*)g_catt;
    const float4* W4 = (const float4*)W;
    u64 acc2[4][12];
    #pragma unroll
    for (int i = 0; i < 4; i++)
        #pragma unroll
        for (int j = 0; j < 12; j++) acc2[i][j] = pack2(0.f, 0.f);
    for (int k0 = 0; k0 < 96; k0 += 8) {
        __syncthreads();
        #pragma unroll
        for (int i = 0; i < 2; i++) {
            int idx = tid + i * 128;
            int r = idx >> 3, kq = idx & 7;
            float4 s = {0.f, 0.f, 0.f, 0.f};
            #pragma unroll
            for (int dir = 0; dir < KDIR_; dir++) {
                float4 y4 = Y4[((size_t)(dir * B_ + b) * L_ + l0 + r) * 96 + k0 + kq];
                float4 c4 = C4[(size_t)(dir * B_ + b) * 96 + k0 + kq];
                s.x += y4.x * c4.x; s.y += y4.y * c4.y;
                s.z += y4.z * c4.z; s.w += y4.w * c4.w;
            }
            As[r][kq] = s;
        }
        #pragma unroll
        for (int i = 0; i < 12; i++) {
            int idx = tid + i * 128;
            int r = idx >> 3, kq = idx & 7;
            Ws[r][kq] = W4[(size_t)r * 96 + k0 + kq];
        }
        __syncthreads();
        #pragma unroll
        for (int kq = 0; kq < 8; kq++) {
            ulonglong2 au[4];
            #pragma unroll
            for (int i = 0; i < 4; i++) au[i] = *(const ulonglong2*)&As[ty * 4 + i][kq];
            #pragma unroll
            for (int j = 0; j < 12; j++) {
                ulonglong2 w = *(const ulonglong2*)&Ws[tx + 16 * j][kq];
                #pragma unroll
                for (int i = 0; i < 4; i++) {
                    acc2[i][j] = fma2(au[i].x, w.x, acc2[i][j]);
                    acc2[i][j] = fma2(au[i].y, w.y, acc2[i][j]);
                }
            }
        }
    }
    #pragma unroll
    for (int i = 0; i < 4; i++)
        #pragma unroll
        for (int j = 0; j < 12; j++) {
            float lo, hi; unpack2(acc2[i][j], lo, hi);
            OUT[(size_t)(m0 + ty * 4 + i) * DM_ + tx + 16 * j] = lo + hi + BI[tx + 16 * j];
        }
}

// ---------------- launch ----------------
extern "C" void kernel_launch(void* const* d_in, const int* in_sizes, int n_in,
                              void* d_out, int out_size) {
    const float* x          = (const float*)d_in[0];
    const float* in_proj_w  = (const float*)d_in[1];
    const float* conv_w     = (const float*)d_in[2];
    const float* conv_b     = (const float*)d_in[3];
    const float* x_proj_w   = (const float*)d_in[4];
    const float* dt_w       = (const float*)d_in[5];
    const float* dt_b       = (const float*)d_in[6];
    const float* A_log      = (const float*)d_in[7];
    const float* D_skip     = (const float*)d_in[8];
    const float* out_proj_w = (const float*)d_in[9];
    const float* out_proj_b = (const float*)d_in[10];
    const float* ln_g       = (const float*)d_in[11];
    const float* ln_b       = (const float*)d_in[12];
    const float* red_w      = (const float*)d_in[13];
    const float* red_b      = (const float*)d_in[14];
    const float* sel_w      = (const float*)d_in[15];
    const float* sel_b      = (const float*)d_in[16];
    const float* mask_w     = (const float*)d_in[17];
    const float* mask_b     = (const float*)d_in[18];
    float* out = (float*)d_out;

    k_mask<<<dim3((B_ * L_ + 7) / 8), dim3(32, 8)>>>(x, mask_w, mask_b);
    k_xz<<<dim3(12, 98), 256>>>(x, in_proj_w);
    k_conv<<<dim3(L_ / 32, 3, KDIR_ * B_), 128>>>(conv_w, conv_b);
    k_xdbl<<<dim3(25, KDIR_ * B_), 128>>>(x_proj_w);
    k_scan1<<<dim3(NCH_, 3, KDIR_ * B_), 128>>>(A_log, dt_w, dt_b);
    k_fix<<<dim3(KDIR_ * B_, 3), 128>>>(A_log);
    k_scan2<<<dim3(NCH_, 3, KDIR_ * B_), 128>>>(A_log, dt_w, dt_b, D_skip);
    k_lnstats<<<dim3(16, B_, KDIR_), 384>>>(ln_g, ln_b);
    k_attn<<<KDIR_ * B_, DIN_>>>(red_w, red_b, sel_w, sel_b);
    k_out<<<dim3(392), 128>>>(out_proj_w, out_proj_b, out);
}